// round 15
// baseline (speedup 1.0000x reference)
#include <cuda_runtime.h>
#include <cuda_bf16.h>

// QuantumLinear: B=4096, IN_F=1024, NQ=4, L=2, C=256 circuits.
// Closed-form <Z_q> via Heisenberg propagation (exact).
// R14: dispatch-occupancy model. Kernel is bound by issue-port cycles
// (MUFU rt8 dominates; all pipes <50% busy is the signature). Levers:
//  (a) perfect CTA balance: grid=592=4x148, every SM gets exactly 4 CTAs,
//      each CTA processes 6-7 CONTIGUOUS rows (ragged split) — removes the
//      16% tail of grid=512 (68 SMs x4 CTAs vs 80 x3).
//  (b) angle adds as FFMA-imm (rt1) instead of FADD (rt2) via inline PTX.
// All-MUFU trig (R7/R13 proved polys cost MORE dispatch than MUFU).

static constexpr int NCIRC = 256;
static constexpr int GRID  = 592;     // 4 x 148 SMs, uniform residency
static constexpr int BROWS = 4096;

// d = a*1.0 + b on the FFMA-imm path (rt_SMSP=1 vs FADD's 2)
__device__ __forceinline__ float add_imm(float a, float b) {
    float d;
    asm("fma.rn.f32 %0, %1, 0f3F800000, %2;" : "=f"(d) : "f"(a), "f"(b));
    return d;
}

struct Coef {
    float a0, a1, a2, a3;      // <Z0>
    float p0, p1, d0, d1;      // <Z1>, <Z2>
    float e0, e1, e2, e3;      // <Z3>
};

__device__ __forceinline__ void do_row(
    const float4 xv, const float4 w0, const Coef& k, float4* dst)
{
    float S0, C0, S1, C1, S2, C2, S3, C3;
    __sincosf(add_imm(xv.x, w0.x), &S0, &C0);
    __sincosf(add_imm(xv.y, w0.y), &S1, &C1);
    __sincosf(add_imm(xv.z, w0.z), &S2, &C2);
    __sincosf(add_imm(xv.w, w0.w), &S3, &C3);

    const float C1C3 = C1 * C3;
    const float S1S3 = S1 * S3;
    const float C0C2 = C0 * C2;
    const float S0S2 = S0 * S2;

    float4 z;
    z.x = fmaf(C1C3, fmaf(k.a0, C0, k.a3 * S0), S1S3 * fmaf(k.a1, S0, k.a2 * C0));
    z.y = C3 * fmaf(k.p0, C0C2, k.p1 * S0S2);
    z.z = fmaf(k.d0, C1C3, k.d1 * S1S3);
    z.w = fmaf(C2, fmaf(k.e0, C0, k.e1 * S0), S2 * fmaf(k.e2, C0, k.e3 * S0));
    *dst = z;
}

__global__ void __launch_bounds__(NCIRC) qfused_kernel(
    const float4* __restrict__ x,     // (B*256) float4
    const float4* __restrict__ w4,    // (256*2) float4  = weights (256,2,4)
    float4* __restrict__ out)         // (B*256) float4
{
    const int c = threadIdx.x;                       // circuit 0..255
    const int i = blockIdx.x;
    // ragged contiguous row split: CTA i owns [i*4096/592, (i+1)*4096/592)
    const int r0    = (i * BROWS) / GRID;            // 6 or 7 rows
    const int nrows = ((i + 1) * BROWS) / GRID - r0;

    const float4 w0 = w4[c * 2 + 0];                 // alpha offsets
    const float4 w1 = w4[c * 2 + 1];                 // beta angles

    // ---- per-circuit coefficients (amortized over 6-7 rows) ----
    float cb0, sb0, cb1, sb1, cb2, sb2, cb3, sb3;
    __sincosf(w1.x, &sb0, &cb0);
    __sincosf(w1.y, &sb1, &cb1);
    __sincosf(w1.z, &sb2, &cb2);
    __sincosf(w1.w, &sb3, &cb3);

    const float c1c2 = cb1 * cb2;
    const float s1s2 = sb1 * sb2;
    Coef k;
    k.a0 = c1c2 * cb3;  k.a1 = c1c2 * sb3;
    k.a2 = s1s2 * cb3;  k.a3 = s1s2 * sb3;
    k.p0 = cb0 * cb1;   k.p1 = sb0 * sb1;
    k.d0 = cb0 * c1c2;  k.d1 = cb0 * s1s2;
    k.e0 = cb0 * c1c2 * cb3;
    k.e1 = cb0 * s1s2 * sb3;
    k.e2 = sb0 * cb1 * sb2 * sb3;
    k.e3 = sb0 * sb1 * cb2 * cb3;

    const float4* xp = x   + r0 * NCIRC + c;
    float4*       op = out + r0 * NCIRC + c;

#pragma unroll
    for (int r = 0; r < 6; r++)
        do_row(xp[r * NCIRC], w0, k, op + r * NCIRC);
    if (nrows == 7)
        do_row(xp[6 * NCIRC], w0, k, op + 6 * NCIRC);
}

extern "C" void kernel_launch(void* const* d_in, const int* in_sizes, int n_in,
                              void* d_out, int out_size) {
    const float* x = (const float*)d_in[0];       // (4096, 1024) f32
    const float* w = (const float*)d_in[1];       // (256, 2, 4)  f32
    float* out = (float*)d_out;                   // (4096, 1024) f32

    qfused_kernel<<<GRID, NCIRC>>>(
        (const float4*)x, (const float4*)w, (float4*)out);
}